// round 1
// baseline (speedup 1.0000x reference)
#include <cuda_runtime.h>
#include <math.h>

// ---------------- fixed problem structure ----------------
#define TT      50      // nodes per tree
#define BRANCH  4
#define D_IN    384
#define HH      512
#define G3      1536
#define MAXB    2000
#define NPAR    13      // parent-capable locals: 0..12

// level layout (local indices within a tree)
//  depth 0: [0,1)   depth 1: [1,5)   depth 2: [5,21)   depth 3: [21,50)

// ---------------- device scratch (static, no allocation) ----------------
__device__ float g_h    [(size_t)MAXB * TT * HH];      // 204.8 MB
__device__ float g_c    [(size_t)MAXB * TT * HH];      // 204.8 MB
__device__ float g_xwf  [(size_t)MAXB * NPAR * HH];    //  53.2 MB
__device__ float g_fc   [(size_t)MAXB * 29 * HH];      // 118.8 MB
__device__ float g_hsum [(size_t)MAXB * 16 * HH];      //  65.5 MB
__device__ float g_fcsum[(size_t)MAXB * 16 * HH];      //  65.5 MB
__device__ float g_gates[(size_t)MAXB * 29 * G3];      // 356.4 MB

// ---------------- helpers ----------------
__device__ __forceinline__ unsigned long long pk2(float x) {
    unsigned long long r;
    asm("mov.b64 %0, {%1, %1};" : "=l"(r) : "f"(x));
    return r;
}
__device__ __forceinline__ unsigned long long fma2(unsigned long long a,
                                                   unsigned long long b,
                                                   unsigned long long c) {
    unsigned long long d;
    asm("fma.rn.f32x2 %0, %1, %2, %3;" : "=l"(d) : "l"(a), "l"(b), "l"(c));
    return d;
}
__device__ __forceinline__ float sigmoidf_(float x) {
    return 1.0f / (1.0f + __expf(-x));
}

// ---------------- GEMM: 128x128 tile, 256 threads, 8x8 micro-tile ----------------
// Pass 0: C += gather(A)[row] @ W      (row gather: tree = r/lcnt, local = lstart + r%lcnt)
// Pass 1: C += A2[row] @ W2            (direct rows), skipped when K2 == 0
// FORGET==0 epilogue: out[row,n] = acc + bias[n]                 (out stride = Nw)
// FORGET==1 epilogue: out[row,n] = sigmoid(acc + xwf[prow,n]) * c[gnode,n]   (Nw=HH)
template<int FORGET>
__global__ __launch_bounds__(256)
void tl_gemm(const float* __restrict__ A,  const float* __restrict__ W,  int K1, int strideA,
             const float* __restrict__ A2, const float* __restrict__ W2, int K2,
             const float* __restrict__ bias,
             const float* __restrict__ xwf, const float* __restrict__ cbuf,
             float* __restrict__ out, int M, int Nw,
             int lstart, int lcnt)
{
    __shared__ float As[16][132];   // +4 pad for store-bank spread; row stride 528B (16B-aligned)
    __shared__ float Bs[16][128];

    const int tid = threadIdx.x;
    const int bm = blockIdx.y * 128;
    const int bn = blockIdx.x * 128;
    const int tx = tid & 15, ty = tid >> 4;

    // A-tile loader: thread loads 2 float4 (rows la and la+64, k-cols acol..acol+3)
    const int la   = tid >> 2;           // 0..63
    const int acol = (tid & 3) << 2;     // 0,4,8,12
    const int arow0 = bm + la;
    const int arow1 = bm + la + 64;
    // B-tile loader: rows lb and lb+8, cols bcol..bcol+3
    const int lb   = tid >> 5;           // 0..7
    const int bcol = (tid & 31) << 2;

    unsigned long long acc[8][4];
    #pragma unroll
    for (int i = 0; i < 8; i++)
        #pragma unroll
        for (int j = 0; j < 4; j++) acc[i][j] = 0ull;

    for (int pass = 0; pass < 2; pass++) {
        const int K = pass ? K2 : K1;
        if (K == 0) continue;
        const float* Wp = pass ? W2 : W;

        // per-thread A row base pointers (fixed across k-tiles)
        const float* pa0;
        const float* pa1;
        {
            int r0 = arow0 < M ? arow0 : M - 1;
            int r1 = arow1 < M ? arow1 : M - 1;
            if (pass == 0) {
                int t0 = r0 / lcnt, l0 = lstart + r0 % lcnt;
                int t1 = r1 / lcnt, l1 = lstart + r1 % lcnt;
                pa0 = A + (size_t)(t0 * TT + l0) * strideA;
                pa1 = A + (size_t)(t1 * TT + l1) * strideA;
            } else {
                pa0 = A2 + (size_t)r0 * K2;
                pa1 = A2 + (size_t)r1 * K2;
            }
        }

        for (int k0 = 0; k0 < K; k0 += 16) {
            float4 a0 = *(const float4*)(pa0 + k0 + acol);
            float4 a1 = *(const float4*)(pa1 + k0 + acol);
            float4 b0 = *(const float4*)(Wp + (size_t)(k0 + lb)     * Nw + bn + bcol);
            float4 b1 = *(const float4*)(Wp + (size_t)(k0 + 8 + lb) * Nw + bn + bcol);

            As[acol + 0][la]      = a0.x; As[acol + 1][la]      = a0.y;
            As[acol + 2][la]      = a0.z; As[acol + 3][la]      = a0.w;
            As[acol + 0][la + 64] = a1.x; As[acol + 1][la + 64] = a1.y;
            As[acol + 2][la + 64] = a1.z; As[acol + 3][la + 64] = a1.w;
            *(float4*)&Bs[lb][bcol]     = b0;
            *(float4*)&Bs[lb + 8][bcol] = b1;
            __syncthreads();

            #pragma unroll
            for (int kk = 0; kk < 16; kk++) {
                float4 av0 = *(const float4*)&As[kk][ty * 8];
                float4 av1 = *(const float4*)&As[kk][ty * 8 + 4];
                unsigned long long bv[4];
                #pragma unroll
                for (int j = 0; j < 4; j++)
                    bv[j] = *(const unsigned long long*)&Bs[kk][tx * 8 + 2 * j];
                float avs[8] = {av0.x, av0.y, av0.z, av0.w, av1.x, av1.y, av1.z, av1.w};
                #pragma unroll
                for (int i = 0; i < 8; i++) {
                    unsigned long long aa = pk2(avs[i]);
                    #pragma unroll
                    for (int j = 0; j < 4; j++)
                        acc[i][j] = fma2(aa, bv[j], acc[i][j]);
                }
            }
            __syncthreads();
        }
    }

    // epilogue
    #pragma unroll
    for (int i = 0; i < 8; i++) {
        int row = bm + ty * 8 + i;
        if (row >= M) break;
        int t = row / lcnt, loc = lstart + row % lcnt;

        if (FORGET) {
            int gnode = t * TT + loc;
            int prow  = t * NPAR + (loc - 1) / BRANCH;
            const float* xrow = xwf  + (size_t)prow  * HH;
            const float* crow = cbuf + (size_t)gnode * HH;
            float* orow = out + (size_t)row * HH;
            #pragma unroll
            for (int j = 0; j < 4; j++) {
                float2 v = *(float2*)&acc[i][j];
                int c0 = bn + tx * 8 + 2 * j;
                float2 r;
                r.x = sigmoidf_(v.x + xrow[c0])     * crow[c0];
                r.y = sigmoidf_(v.y + xrow[c0 + 1]) * crow[c0 + 1];
                *(float2*)&orow[c0] = r;
            }
        } else {
            float* orow = out + (size_t)row * Nw;
            #pragma unroll
            for (int j = 0; j < 4; j++) {
                float2 v = *(float2*)&acc[i][j];
                int c0 = bn + tx * 8 + 2 * j;
                float2 r;
                r.x = v.x + bias[c0];
                r.y = v.y + bias[c0 + 1];
                *(float2*)&orow[c0] = r;
            }
        }
    }
}

// ---------------- child-message reduction (4 children per parent, fixed topology) ----
__global__ void tl_reduce(const float* __restrict__ h, const float* __restrict__ fc,
                          float* __restrict__ hsum, float* __restrict__ fcsum,
                          int B, int Pstart, int Pcnt, int Cstart, int Ccnt)
{
    int total = B * Pcnt * HH;
    for (int idx = blockIdx.x * blockDim.x + threadIdx.x; idx < total;
         idx += gridDim.x * blockDim.x) {
        int n = idx & (HH - 1);
        int prow = idx >> 9;                 // HH = 512
        int t = prow / Pcnt;
        int pl = Pstart + prow % Pcnt;
        float hs = 0.f, fs = 0.f;
        #pragma unroll
        for (int cg = 0; cg < BRANCH; cg++) {
            int cl = BRANCH * pl + 1 + cg;
            if (cl < TT) {
                hs += h[(size_t)(t * TT + cl) * HH + n];
                fs += fc[(size_t)(t * Ccnt + cl - Cstart) * HH + n];
            }
        }
        hsum [(size_t)prow * HH + n] = hs;
        fcsum[(size_t)prow * HH + n] = fs;
    }
}

// ---------------- LSTM cell nonlinearity over one level ----------------
__global__ void tl_cell(const float* __restrict__ gates, const float* __restrict__ fcsum,
                        float* __restrict__ h, float* __restrict__ c,
                        int B, int Lstart, int Lcnt, int haschild)
{
    int total = B * Lcnt * HH;
    for (int idx = blockIdx.x * blockDim.x + threadIdx.x; idx < total;
         idx += gridDim.x * blockDim.x) {
        int n = idx & (HH - 1);
        int row = idx >> 9;
        int t = row / Lcnt, loc = Lstart + row % Lcnt;
        size_t gb = (size_t)row * G3;
        float iv = gates[gb + n];
        float ov = gates[gb + HH + n];
        float uv = gates[gb + 2 * HH + n];
        float cn = sigmoidf_(iv) * tanhf(uv) + (haschild ? fcsum[(size_t)row * HH + n] : 0.f);
        float hn = sigmoidf_(ov) * tanhf(cn);
        size_t gn = (size_t)(t * TT + loc) * HH + n;
        h[gn] = hn;
        c[gn] = cn;
    }
}

// ---------------- readout: per-graph sum + split + tanh ----------------
__global__ void tl_readout(const float* __restrict__ h, float* __restrict__ out, int B)
{
    int g = blockIdx.x;
    for (int n = threadIdx.x; n < HH; n += blockDim.x) {
        const float* hp = h + (size_t)g * TT * HH + n;
        float s = 0.f;
        #pragma unroll
        for (int tn = 0; tn < TT; tn++) s += hp[(size_t)tn * HH];
        if (n < 256) out[(size_t)g * 256 + n] = s;                         // graph_mu
        else out[(size_t)B * 256 + (size_t)g * 256 + (n - 256)] = tanhf(s); // tanh(logvar)
    }
}

// ---------------- launch ----------------
extern "C" void kernel_launch(void* const* d_in, const int* in_sizes, int n_in,
                              void* d_out, int out_size)
{
    const float* embed = (const float*)d_in[0];
    const float* W_iou = (const float*)d_in[1];
    const float* U_iou = (const float*)d_in[2];
    const float* b_iou = (const float*)d_in[3];
    const float* W_f   = (const float*)d_in[4];
    const float* U_f   = (const float*)d_in[5];
    const float* b_f   = (const float*)d_in[6];

    int N = in_sizes[0] / D_IN;
    int B = N / TT;
    if (B > MAXB) B = MAXB;

    float *h, *c, *xwf, *fc, *hsum, *fcsum, *gates;
    cudaGetSymbolAddress((void**)&h,     g_h);
    cudaGetSymbolAddress((void**)&c,     g_c);
    cudaGetSymbolAddress((void**)&xwf,   g_xwf);
    cudaGetSymbolAddress((void**)&fc,    g_fc);
    cudaGetSymbolAddress((void**)&hsum,  g_hsum);
    cudaGetSymbolAddress((void**)&fcsum, g_fcsum);
    cudaGetSymbolAddress((void**)&gates, g_gates);

    dim3 blk(256);
    #define GY(M) (((M) + 127) / 128)

    // xWf for all parent-capable nodes (locals 0..12)
    tl_gemm<0><<<dim3(HH / 128, GY(B * NPAR)), blk>>>(
        embed, W_f, D_IN, D_IN, nullptr, nullptr, 0,
        b_f, nullptr, nullptr, xwf, B * NPAR, HH, 0, NPAR);

    // level 3 (leaves-deepest): gates = E@W_iou + b, no children
    tl_gemm<0><<<dim3(G3 / 128, GY(B * 29)), blk>>>(
        embed, W_iou, D_IN, D_IN, nullptr, nullptr, 0,
        b_iou, nullptr, nullptr, gates, B * 29, G3, 21, 29);
    tl_cell<<<2048, 256>>>(gates, nullptr, h, c, B, 21, 29, 0);

    // levels 2,1,0
    const int lp[3][4] = { {5, 16, 21, 29}, {1, 4, 5, 16}, {0, 1, 1, 4} };
    for (int li = 0; li < 3; li++) {
        int Pstart = lp[li][0], Pcnt = lp[li][1], Cstart = lp[li][2], Ccnt = lp[li][3];

        // fc = sigmoid(h_child @ U_f + xWf[parent]) * c_child
        tl_gemm<1><<<dim3(HH / 128, GY(B * Ccnt)), blk>>>(
            h, U_f, HH, HH, nullptr, nullptr, 0,
            nullptr, xwf, c, fc, B * Ccnt, HH, Cstart, Ccnt);

        tl_reduce<<<2048, 256>>>(h, fc, hsum, fcsum, B, Pstart, Pcnt, Cstart, Ccnt);

        // gates = E@W_iou + hsum@U_iou + b
        tl_gemm<0><<<dim3(G3 / 128, GY(B * Pcnt)), blk>>>(
            embed, W_iou, D_IN, D_IN, hsum, U_iou, HH,
            b_iou, nullptr, nullptr, gates, B * Pcnt, G3, Pstart, Pcnt);

        tl_cell<<<2048, 256>>>(gates, fcsum, h, c, B, Pstart, Pcnt, 1);
    }

    tl_readout<<<B, 256>>>(h, (float*)d_out, B);
    #undef GY
}

// round 3
// speedup vs baseline: 2.8749x; 2.8749x over previous
#include <cuda_runtime.h>
#include <cuda_fp16.h>
#include <cstdint>
#include <math.h>

// ---------------- fixed problem structure ----------------
#define TT      50
#define BRANCH  4
#define D_IN    384
#define HH      512
#define G3      1536
#define MAXB    2000
#define NPAR    13
#define NNODE   (MAXB * TT)

// ---------------- device scratch ----------------
__device__ float  g_h    [(size_t)NNODE * HH];
__device__ float  g_c    [(size_t)NNODE * HH];
__device__ float  g_xwf  [(size_t)MAXB * NPAR * HH];
__device__ float  g_fc   [(size_t)MAXB * 29 * HH];
__device__ float  g_fcsum[(size_t)MAXB * 16 * HH];
__device__ float  g_gates[(size_t)MAXB * 29 * G3];
__device__ __half g_e16  [(size_t)NNODE * D_IN];
__device__ __half g_h16  [(size_t)NNODE * HH];
__device__ __half g_hsum16[(size_t)MAXB * 16 * HH];
__device__ __half g_Wt_iou[G3 * D_IN];   // fp16, K-major [N][K]
__device__ __half g_Ut_iou[G3 * HH];
__device__ __half g_Wt_f  [HH * D_IN];
__device__ __half g_Ut_f  [HH * HH];

// ---------------- PTX helpers (portable ISA only: sm_80-level) ----------------
__device__ __forceinline__ uint32_t s2u(const void* p) {
    uint32_t a;
    asm("{ .reg .u64 t; cvta.to.shared.u64 t, %1; cvt.u32.u64 %0, t; }" : "=r"(a) : "l"(p));
    return a;
}
__device__ __forceinline__ void cpasync16(uint32_t dst, const void* src) {
    asm volatile("cp.async.cg.shared.global [%0], [%1], 16;" :: "r"(dst), "l"(src));
}
__device__ __forceinline__ void cpcommit() {
    asm volatile("cp.async.commit_group;" ::: "memory");
}
template<int N>
__device__ __forceinline__ void cpwait() {
    asm volatile("cp.async.wait_group %0;" :: "n"(N) : "memory");
}
__device__ __forceinline__ void ldsm4(uint32_t& r0, uint32_t& r1, uint32_t& r2, uint32_t& r3,
                                      uint32_t a) {
    asm volatile("ldmatrix.sync.aligned.m8n8.x4.shared.b16 {%0,%1,%2,%3}, [%4];"
                 : "=r"(r0), "=r"(r1), "=r"(r2), "=r"(r3) : "r"(a));
}
__device__ __forceinline__ void mma16816(float* c,
                                         uint32_t a0, uint32_t a1, uint32_t a2, uint32_t a3,
                                         uint32_t b0, uint32_t b1) {
    asm volatile(
        "mma.sync.aligned.m16n8k16.row.col.f32.f16.f16.f32 "
        "{%0,%1,%2,%3}, {%4,%5,%6,%7}, {%8,%9}, {%0,%1,%2,%3};"
        : "+f"(c[0]), "+f"(c[1]), "+f"(c[2]), "+f"(c[3])
        : "r"(a0), "r"(a1), "r"(a2), "r"(a3), "r"(b0), "r"(b1));
}
__device__ __forceinline__ float sigmoidf_(float x) { return 1.0f / (1.0f + __expf(-x)); }

// ---------------- GEMM tiling constants ----------------
#define STAGES 3
#define BK     32                      // halves per k-chunk
#define ROWB   80                      // smem row stride in bytes (40 halves, conflict-free)
#define ASTG   (128 * ROWB)            // 10240 B per stage (A or B)
#define SMTOT  (STAGES * 2 * ASTG)     // 61440 B

// ============================================================================
// hgemm: out[M x 128-slice of Nw] = gather(A)[M,K1] @ B1^T (+ A2[M,K2] @ B2^T)
//   A gather: row r -> tree t = r/lcnt, local = lstart + r%lcnt, A + (t*TT+local)*strideA
//   B1/B2 are fp16 K-major [N][K]. bn = blockIdx.x*128.
// FORGET==0: out[row*Nw + c] = acc + bias[c]
// FORGET==1: out[row*HH + c] = sigmoid(acc + xwf[prow*HH+c]) * cbuf[gnode*HH+c]
// 256 threads, 8 warps (2m x 4n), warp tile 64x32, mma.sync m16n8k16 fp16->fp32.
// ============================================================================
template<int FORGET>
__global__ void __launch_bounds__(256, 1)
hgemm(const __half* __restrict__ A,  const __half* __restrict__ B1, int K1, int strideA,
      const __half* __restrict__ A2, const __half* __restrict__ B2, int K2,
      const float* __restrict__ bias, const float* __restrict__ xwf,
      const float* __restrict__ cbuf,
      float* __restrict__ out, int M, int Nw, int lstart, int lcnt)
{
    extern __shared__ char smraw[];
    const uint32_t sb = s2u(smraw);

    const int tid  = threadIdx.x;
    const int lane = tid & 31;
    const int wid  = tid >> 5;
    const int wm   = wid >> 2;          // 0..1
    const int wn   = wid & 3;           // 0..3
    const int bm   = blockIdx.y * 128;
    const int bn   = blockIdx.x * 128;

    // ---- cp.async loader assignment: rows lr0 / lr0+64, 16B chunk kc ----
    const int lr0 = tid >> 2;           // 0..63
    const int lr1 = lr0 + 64;
    const int kc  = tid & 3;            // 0..3 (x 16B)

    const __half *a1p0, *a1p1, *a2p0 = nullptr, *a2p1 = nullptr;
    {
        int r0 = bm + lr0; if (r0 >= M) r0 = M - 1;
        int r1 = bm + lr1; if (r1 >= M) r1 = M - 1;
        int t0 = r0 / lcnt, l0 = lstart + r0 % lcnt;
        int t1 = r1 / lcnt, l1 = lstart + r1 % lcnt;
        a1p0 = A + (size_t)(t0 * TT + l0) * strideA;
        a1p1 = A + (size_t)(t1 * TT + l1) * strideA;
        if (K2 > 0) {
            a2p0 = A2 + (size_t)r0 * K2;
            a2p1 = A2 + (size_t)r1 * K2;
        }
    }
    const __half* b1p0 = B1 + (size_t)(bn + lr0) * K1;
    const __half* b1p1 = B1 + (size_t)(bn + lr1) * K1;
    const __half* b2p0 = (K2 > 0) ? B2 + (size_t)(bn + lr0) * K2 : nullptr;
    const __half* b2p1 = (K2 > 0) ? B2 + (size_t)(bn + lr1) * K2 : nullptr;

    const int n1 = K1 / BK, n2 = (K2 > 0) ? K2 / BK : 0, nt = n1 + n2;

    auto issue = [&](int ci, int s) {
        const bool p2 = (ci >= n1);
        const int  kb = (p2 ? (ci - n1) : ci) * BK + kc * 8;   // halves
        const __half* ar0 = p2 ? a2p0 : a1p0;
        const __half* ar1 = p2 ? a2p1 : a1p1;
        const __half* br0 = p2 ? b2p0 : b1p0;
        const __half* br1 = p2 ? b2p1 : b1p1;
        const uint32_t as = sb + s * ASTG;
        const uint32_t bs = sb + STAGES * ASTG + s * ASTG;
        cpasync16(as + lr0 * ROWB + kc * 16, ar0 + kb);
        cpasync16(as + lr1 * ROWB + kc * 16, ar1 + kb);
        cpasync16(bs + lr0 * ROWB + kc * 16, br0 + kb);
        cpasync16(bs + lr1 * ROWB + kc * 16, br1 + kb);
    };

    // ---- ldmatrix per-thread offsets (byte offsets within a stage) ----
    uint32_t aoff[4], boff[2];
    {
        const int rl = (lane & 7) + ((lane >> 3) & 1) * 8;
        const int kq = (lane >> 4) * 16;                 // bytes
        #pragma unroll
        for (int i = 0; i < 4; i++)
            aoff[i] = (uint32_t)((wm * 64 + i * 16 + rl) * ROWB + kq);
        const int nl  = (lane & 7) + (lane >> 4) * 8;
        const int kb2 = ((lane >> 3) & 1) * 16;          // bytes
        #pragma unroll
        for (int p = 0; p < 2; p++)
            boff[p] = (uint32_t)((wn * 32 + p * 16 + nl) * ROWB + kb2);
    }

    float acc[4][4][4];
    #pragma unroll
    for (int i = 0; i < 4; i++)
        #pragma unroll
        for (int j = 0; j < 4; j++)
            #pragma unroll
            for (int q = 0; q < 4; q++) acc[i][j][q] = 0.f;

    // prologue: fill STAGES-1 stages
    #pragma unroll
    for (int s = 0; s < STAGES - 1; s++) { issue(s, s); cpcommit(); }

    for (int ci = 0; ci < nt; ci++) {
        cpwait<STAGES - 2>();
        __syncthreads();

        const int pre = ci + STAGES - 1;
        if (pre < nt) issue(pre, pre % STAGES);
        cpcommit();

        const uint32_t as = sb + (ci % STAGES) * ASTG;
        const uint32_t bs = as + STAGES * ASTG;

        #pragma unroll
        for (int ks = 0; ks < 2; ks++) {
            uint32_t af[4][4], bf[2][4];
            #pragma unroll
            for (int i = 0; i < 4; i++)
                ldsm4(af[i][0], af[i][1], af[i][2], af[i][3], as + aoff[i] + ks * 32);
            #pragma unroll
            for (int p = 0; p < 2; p++)
                ldsm4(bf[p][0], bf[p][1], bf[p][2], bf[p][3], bs + boff[p] + ks * 32);
            #pragma unroll
            for (int i = 0; i < 4; i++)
                #pragma unroll
                for (int j = 0; j < 4; j++)
                    mma16816(acc[i][j], af[i][0], af[i][1], af[i][2], af[i][3],
                             bf[j >> 1][(j & 1) * 2], bf[j >> 1][(j & 1) * 2 + 1]);
        }
    }

    // ---- epilogue ----
    const int g  = lane >> 2;
    const int cq = (lane & 3) * 2;
    #pragma unroll
    for (int mi = 0; mi < 4; mi++) {
        #pragma unroll
        for (int half = 0; half < 2; half++) {
            const int row = bm + wm * 64 + mi * 16 + g + half * 8;
            if (row >= M) continue;
            const float* xrow = nullptr;
            const float* crow = nullptr;
            float* orow;
            if (FORGET) {
                const int t = row / lcnt, loc = lstart + row % lcnt;
                xrow = xwf  + (size_t)(t * NPAR + (loc - 1) / BRANCH) * HH;
                crow = cbuf + (size_t)(t * TT + loc) * HH;
                orow = out  + (size_t)row * HH;
            } else {
                orow = out + (size_t)row * Nw;
            }
            #pragma unroll
            for (int nj = 0; nj < 4; nj++) {
                const int col = bn + wn * 32 + nj * 8 + cq;
                float v0 = acc[mi][nj][half * 2 + 0];
                float v1 = acc[mi][nj][half * 2 + 1];
                float2 r;
                if (FORGET) {
                    float2 xr = *(const float2*)(xrow + col);
                    float2 cr = *(const float2*)(crow + col);
                    r.x = sigmoidf_(v0 + xr.x) * cr.x;
                    r.y = sigmoidf_(v1 + xr.y) * cr.y;
                } else {
                    float2 bb = *(const float2*)(bias + col);
                    r.x = v0 + bb.x;
                    r.y = v1 + bb.y;
                }
                *(float2*)(orow + col) = r;
            }
        }
    }
}

// ---------------- fp32 -> fp16 cast (embed) ----------------
__global__ void cvt16(const float* __restrict__ in, __half* __restrict__ o, int n2) {
    for (int i = blockIdx.x * blockDim.x + threadIdx.x; i < n2;
         i += gridDim.x * blockDim.x) {
        float2 v = ((const float2*)in)[i];
        ((__half2*)o)[i] = __floats2half2_rn(v.x, v.y);
    }
}

// ---------------- weight transpose + convert: Wt16[n*K+k] = W[k*N+n] ----------------
__global__ void wtrans16(const float* __restrict__ W, __half* __restrict__ Wt,
                         int K, int N)
{
    __shared__ float t[32][33];
    const int bx = blockIdx.x * 32;   // n
    const int by = blockIdx.y * 32;   // k
    const int x = threadIdx.x, y = threadIdx.y;
    #pragma unroll
    for (int i = 0; i < 32; i += 8)
        t[y + i][x] = W[(size_t)(by + y + i) * N + bx + x];
    __syncthreads();
    #pragma unroll
    for (int i = 0; i < 32; i += 8)
        Wt[(size_t)(bx + y + i) * K + by + x] = __float2half(t[x][y + i]);
}

// ---------------- child-message reduction (hsum in fp16, fcsum fp32) ----------------
__global__ void tl_reduce(const float* __restrict__ h, const float* __restrict__ fc,
                          __half* __restrict__ hsum16, float* __restrict__ fcsum,
                          int B, int Pstart, int Pcnt, int Cstart, int Ccnt)
{
    int total = B * Pcnt * HH;
    for (int idx = blockIdx.x * blockDim.x + threadIdx.x; idx < total;
         idx += gridDim.x * blockDim.x) {
        int n = idx & (HH - 1);
        int prow = idx >> 9;
        int t = prow / Pcnt;
        int pl = Pstart + prow % Pcnt;
        float hs = 0.f, fs = 0.f;
        #pragma unroll
        for (int cg = 0; cg < BRANCH; cg++) {
            int cl = BRANCH * pl + 1 + cg;
            if (cl < TT) {
                hs += h[(size_t)(t * TT + cl) * HH + n];
                fs += fc[(size_t)(t * Ccnt + cl - Cstart) * HH + n];
            }
        }
        hsum16[(size_t)prow * HH + n] = __float2half(hs);
        fcsum [(size_t)prow * HH + n] = fs;
    }
}

// ---------------- LSTM cell (writes h fp32 + fp16, c fp32) ----------------
__global__ void tl_cell(const float* __restrict__ gates, const float* __restrict__ fcsum,
                        float* __restrict__ h, float* __restrict__ c,
                        __half* __restrict__ h16,
                        int B, int Lstart, int Lcnt, int haschild)
{
    int total = B * Lcnt * HH;
    for (int idx = blockIdx.x * blockDim.x + threadIdx.x; idx < total;
         idx += gridDim.x * blockDim.x) {
        int n = idx & (HH - 1);
        int row = idx >> 9;
        int t = row / Lcnt, loc = Lstart + row % Lcnt;
        size_t gb = (size_t)row * G3;
        float iv = gates[gb + n];
        float ov = gates[gb + HH + n];
        float uv = gates[gb + 2 * HH + n];
        float cn = sigmoidf_(iv) * tanhf(uv) + (haschild ? fcsum[(size_t)row * HH + n] : 0.f);
        float hn = sigmoidf_(ov) * tanhf(cn);
        size_t gn = (size_t)(t * TT + loc) * HH + n;
        h[gn]   = hn;
        c[gn]   = cn;
        h16[gn] = __float2half(hn);
    }
}

// ---------------- readout ----------------
__global__ void tl_readout(const float* __restrict__ h, float* __restrict__ out, int B)
{
    int g = blockIdx.x;
    for (int n = threadIdx.x; n < HH; n += blockDim.x) {
        const float* hp = h + (size_t)g * TT * HH + n;
        float s = 0.f;
        #pragma unroll
        for (int tn = 0; tn < TT; tn++) s += hp[(size_t)tn * HH];
        if (n < 256) out[(size_t)g * 256 + n] = s;
        else out[(size_t)B * 256 + (size_t)g * 256 + (n - 256)] = tanhf(s);
    }
}

// ---------------- launch ----------------
extern "C" void kernel_launch(void* const* d_in, const int* in_sizes, int n_in,
                              void* d_out, int out_size)
{
    const float* embed = (const float*)d_in[0];
    const float* W_iou = (const float*)d_in[1];
    const float* U_iou = (const float*)d_in[2];
    const float* b_iou = (const float*)d_in[3];
    const float* W_f   = (const float*)d_in[4];
    const float* U_f   = (const float*)d_in[5];
    const float* b_f   = (const float*)d_in[6];

    int N = in_sizes[0] / D_IN;
    int B = N / TT;
    if (B > MAXB) B = MAXB;

    float *h, *c, *xwf, *fc, *fcsum, *gates;
    __half *e16, *h16, *hsum16, *Wt_iou, *Ut_iou, *Wt_f, *Ut_f;
    cudaGetSymbolAddress((void**)&h,      g_h);
    cudaGetSymbolAddress((void**)&c,      g_c);
    cudaGetSymbolAddress((void**)&xwf,    g_xwf);
    cudaGetSymbolAddress((void**)&fc,     g_fc);
    cudaGetSymbolAddress((void**)&fcsum,  g_fcsum);
    cudaGetSymbolAddress((void**)&gates,  g_gates);
    cudaGetSymbolAddress((void**)&e16,    g_e16);
    cudaGetSymbolAddress((void**)&h16,    g_h16);
    cudaGetSymbolAddress((void**)&hsum16, g_hsum16);
    cudaGetSymbolAddress((void**)&Wt_iou, g_Wt_iou);
    cudaGetSymbolAddress((void**)&Ut_iou, g_Ut_iou);
    cudaGetSymbolAddress((void**)&Wt_f,   g_Wt_f);
    cudaGetSymbolAddress((void**)&Ut_f,   g_Ut_f);

    cudaFuncSetAttribute(hgemm<0>, cudaFuncAttributeMaxDynamicSharedMemorySize, SMTOT);
    cudaFuncSetAttribute(hgemm<1>, cudaFuncAttributeMaxDynamicSharedMemorySize, SMTOT);

    // conversions
    cvt16<<<4096, 256>>>(embed, e16, B * TT * D_IN / 2);
    dim3 tb(32, 8);
    wtrans16<<<dim3(G3 / 32, D_IN / 32), tb>>>(W_iou, Wt_iou, D_IN, G3);
    wtrans16<<<dim3(G3 / 32, HH / 32),   tb>>>(U_iou, Ut_iou, HH,   G3);
    wtrans16<<<dim3(HH / 32, D_IN / 32), tb>>>(W_f,   Wt_f,   D_IN, HH);
    wtrans16<<<dim3(HH / 32, HH / 32),   tb>>>(U_f,   Ut_f,   HH,   HH);

    #define GY(M) (((M) + 127) / 128)

    // xWf for parent-capable nodes (locals 0..12)
    hgemm<0><<<dim3(HH / 128, GY(B * NPAR)), 256, SMTOT>>>(
        e16, Wt_f, D_IN, D_IN, nullptr, nullptr, 0,
        b_f, nullptr, nullptr, xwf, B * NPAR, HH, 0, NPAR);

    // level 3 (deepest): gates = E@W_iou + b
    hgemm<0><<<dim3(G3 / 128, GY(B * 29)), 256, SMTOT>>>(
        e16, Wt_iou, D_IN, D_IN, nullptr, nullptr, 0,
        b_iou, nullptr, nullptr, gates, B * 29, G3, 21, 29);
    tl_cell<<<2048, 256>>>(gates, nullptr, h, c, h16, B, 21, 29, 0);

    const int lp[3][4] = { {5, 16, 21, 29}, {1, 4, 5, 16}, {0, 1, 1, 4} };
    for (int li = 0; li < 3; li++) {
        int Pstart = lp[li][0], Pcnt = lp[li][1], Cstart = lp[li][2], Ccnt = lp[li][3];

        // fc = sigmoid(h_child @ U_f + xWf[parent]) * c_child
        hgemm<1><<<dim3(HH / 128, GY(B * Ccnt)), 256, SMTOT>>>(
            h16, Ut_f, HH, HH, nullptr, nullptr, 0,
            nullptr, xwf, c, fc, B * Ccnt, HH, Cstart, Ccnt);

        tl_reduce<<<2048, 256>>>(h, fc, hsum16, fcsum, B, Pstart, Pcnt, Cstart, Ccnt);

        // gates = E@W_iou + hsum@U_iou + b
        hgemm<0><<<dim3(G3 / 128, GY(B * Pcnt)), 256, SMTOT>>>(
            e16, Wt_iou, D_IN, D_IN, hsum16, Ut_iou, HH,
            b_iou, nullptr, nullptr, gates, B * Pcnt, G3, Pstart, Pcnt);

        tl_cell<<<2048, 256>>>(gates, fcsum, h, c, h16, B, Pstart, Pcnt, 1);
    }

    tl_readout<<<B, 256>>>(h, (float*)d_out, B);
    #undef GY
}

// round 4
// speedup vs baseline: 3.5436x; 1.2326x over previous
#include <cuda_runtime.h>
#include <cuda_fp16.h>
#include <cstdint>
#include <math.h>

// ---------------- fixed problem structure ----------------
#define TT      50
#define BRANCH  4
#define D_IN    384
#define HH      512
#define G3      1536
#define MAXB    2000
#define NPAR    13
#define NNODE   (MAXB * TT)

// ---------------- device scratch ----------------
__device__ float  g_h    [(size_t)NNODE * HH];
__device__ float  g_c    [(size_t)NNODE * HH];
__device__ float  g_xwf  [(size_t)MAXB * NPAR * HH];
__device__ float  g_fc   [(size_t)MAXB * 29 * HH];
__device__ float  g_fcsum[(size_t)MAXB * 16 * HH];
__device__ __half g_e16  [(size_t)NNODE * D_IN];
__device__ __half g_h16  [(size_t)NNODE * HH];
__device__ __half g_hsum16[(size_t)MAXB * 16 * HH];
__device__ __half g_Wt_iou[G3 * D_IN];   // fp16, K-major [N'][K], gate-interleaved N'
__device__ __half g_Ut_iou[G3 * HH];     // gate-interleaved N'
__device__ __half g_Wt_f  [HH * D_IN];
__device__ __half g_Ut_f  [HH * HH];

// ---------------- PTX helpers (portable ISA: sm_80-level) ----------------
__device__ __forceinline__ uint32_t s2u(const void* p) {
    uint32_t a;
    asm("{ .reg .u64 t; cvta.to.shared.u64 t, %1; cvt.u32.u64 %0, t; }" : "=r"(a) : "l"(p));
    return a;
}
__device__ __forceinline__ void cpasync16(uint32_t dst, const void* src) {
    asm volatile("cp.async.cg.shared.global [%0], [%1], 16;" :: "r"(dst), "l"(src));
}
__device__ __forceinline__ void cpcommit() {
    asm volatile("cp.async.commit_group;" ::: "memory");
}
template<int N>
__device__ __forceinline__ void cpwait() {
    asm volatile("cp.async.wait_group %0;" :: "n"(N) : "memory");
}
__device__ __forceinline__ void ldsm4(uint32_t& r0, uint32_t& r1, uint32_t& r2, uint32_t& r3,
                                      uint32_t a) {
    asm volatile("ldmatrix.sync.aligned.m8n8.x4.shared.b16 {%0,%1,%2,%3}, [%4];"
                 : "=r"(r0), "=r"(r1), "=r"(r2), "=r"(r3) : "r"(a));
}
__device__ __forceinline__ void ldsm2(uint32_t& r0, uint32_t& r1, uint32_t a) {
    asm volatile("ldmatrix.sync.aligned.m8n8.x2.shared.b16 {%0,%1}, [%2];"
                 : "=r"(r0), "=r"(r1) : "r"(a));
}
__device__ __forceinline__ void mma16816(float* c,
                                         uint32_t a0, uint32_t a1, uint32_t a2, uint32_t a3,
                                         uint32_t b0, uint32_t b1) {
    asm volatile(
        "mma.sync.aligned.m16n8k16.row.col.f32.f16.f16.f32 "
        "{%0,%1,%2,%3}, {%4,%5,%6,%7}, {%8,%9}, {%0,%1,%2,%3};"
        : "+f"(c[0]), "+f"(c[1]), "+f"(c[2]), "+f"(c[3])
        : "r"(a0), "r"(a1), "r"(a2), "r"(a3), "r"(b0), "r"(b1));
}
__device__ __forceinline__ float sigmoidf_(float x) { return 1.0f / (1.0f + __expf(-x)); }

// ---------------- GEMM tiling ----------------
#define STAGES 3
#define BK     32                      // halves per k-chunk
#define ROWB   80                      // smem row stride (bytes)
#define ASTG   (128 * ROWB)            // A stage: 128 rows

// MODE 0: out = acc + bias                       (NT=128)
// MODE 1: out = sigmoid(acc + xwf[parent]) * c   (NT=128)
// MODE 2: fused LSTM cell; gate-interleaved cols (NT=96, warp 64x24 = [i8|o8|u8])
template<int MODE, int NT>
__global__ void __launch_bounds__(256, (MODE == 2) ? 2 : 1)
hgemm(const __half* __restrict__ A,  const __half* __restrict__ B1, int K1, int strideA,
      const __half* __restrict__ A2, const __half* __restrict__ B2, int K2,
      const float* __restrict__ bias, const float* __restrict__ xwf,
      const float* __restrict__ cbuf,
      float* __restrict__ out,
      float* __restrict__ hout, float* __restrict__ cout, __half* __restrict__ h16out,
      const float* __restrict__ fcsum,
      int M, int Nw, int lstart, int lcnt)
{
    constexpr int NJ   = NT / 32;              // n-fragments per warp: 4 (NT=128) or 3 (NT=96)
    constexpr int BSTG = NT * ROWB;
    constexpr int NB   = (NT * 4 + 255) / 256; // B cp.async chunks per thread (=2)

    extern __shared__ char smraw[];
    const uint32_t sb  = s2u(smraw);
    const uint32_t sbB = sb + STAGES * ASTG;

    const int tid  = threadIdx.x;
    const int lane = tid & 31;
    const int wid  = tid >> 5;
    const int wm   = wid >> 2;
    const int wn   = wid & 3;
    const int bm   = blockIdx.y * 128;
    const int bn   = blockIdx.x * NT;

    // ---- A loader: rows lr0/lr0+64, chunk kc ----
    const int lr0 = tid >> 2;
    const int lr1 = lr0 + 64;
    const int kc  = tid & 3;
    const __half *a1p0, *a1p1, *a2p0 = nullptr, *a2p1 = nullptr;
    {
        int r0 = bm + lr0; if (r0 >= M) r0 = M - 1;
        int r1 = bm + lr1; if (r1 >= M) r1 = M - 1;
        int t0 = r0 / lcnt, l0 = lstart + r0 % lcnt;
        int t1 = r1 / lcnt, l1 = lstart + r1 % lcnt;
        a1p0 = A + (size_t)(t0 * TT + l0) * strideA + kc * 8;
        a1p1 = A + (size_t)(t1 * TT + l1) * strideA + kc * 8;
        if (K2 > 0) {
            a2p0 = A2 + (size_t)r0 * K2 + kc * 8;
            a2p1 = A2 + (size_t)r1 * K2 + kc * 8;
        }
    }
    const uint32_t as0 = (uint32_t)(lr0 * ROWB + kc * 16);
    const uint32_t as1 = (uint32_t)(lr1 * ROWB + kc * 16);

    // ---- B loader: NB chunks per thread ----
    const __half* pb1[NB];
    const __half* pb2[NB];
    uint32_t bso[NB];
    bool bok[NB];
    #pragma unroll
    for (int i = 0; i < NB; i++) {
        int idx = tid + i * 256;
        bok[i] = idx < NT * 4;
        int row = bok[i] ? (idx >> 2) : 0;
        int ch  = idx & 3;
        pb1[i] = B1 + (size_t)(bn + row) * K1 + ch * 8;
        pb2[i] = (K2 > 0) ? B2 + (size_t)(bn + row) * K2 + ch * 8 : nullptr;
        bso[i] = (uint32_t)(row * ROWB + ch * 16);
    }

    const int n1 = K1 / BK, n2 = (K2 > 0) ? K2 / BK : 0, nt = n1 + n2;

    auto issue = [&](int ci, int s) {
        const bool p2 = (ci >= n1);
        const int  kb = (p2 ? (ci - n1) : ci) * BK;
        const uint32_t abase = sb  + s * ASTG;
        const uint32_t bbase = sbB + s * BSTG;
        cpasync16(abase + as0, (p2 ? a2p0 : a1p0) + kb);
        cpasync16(abase + as1, (p2 ? a2p1 : a1p1) + kb);
        #pragma unroll
        for (int i = 0; i < NB; i++)
            if (bok[i]) cpasync16(bbase + bso[i], (p2 ? pb2[i] : pb1[i]) + kb);
    };

    // ---- ldmatrix offsets ----
    uint32_t aoff[4];
    {
        const int rl = (lane & 7) + ((lane >> 3) & 1) * 8;
        const int kq = (lane >> 4) * 16;
        #pragma unroll
        for (int i = 0; i < 4; i++)
            aoff[i] = (uint32_t)((wm * 64 + i * 16 + rl) * ROWB + kq);
    }
    const int nl  = (lane & 7) + (lane >> 4) * 8;
    const int kb2 = ((lane >> 3) & 1) * 16;
    const int WNT = NT / 4;                           // warp n width: 32 or 24
    const uint32_t boff0 = (uint32_t)((wn * WNT + nl) * ROWB + kb2);          // n 0..15
    const uint32_t boff1 = (NJ == 4)
        ? (uint32_t)((wn * WNT + 16 + nl) * ROWB + kb2)                        // n 16..31 (x4)
        : (uint32_t)((wn * WNT + 16 + (lane & 7)) * ROWB + kb2);               // n 16..23 (x2)

    float acc[4][NJ][4];
    #pragma unroll
    for (int i = 0; i < 4; i++)
        #pragma unroll
        for (int j = 0; j < NJ; j++)
            #pragma unroll
            for (int q = 0; q < 4; q++) acc[i][j][q] = 0.f;

    #pragma unroll
    for (int s = 0; s < STAGES - 1; s++) { issue(s, s); cpcommit(); }

    for (int ci = 0; ci < nt; ci++) {
        cpwait<STAGES - 2>();
        __syncthreads();

        const int pre = ci + STAGES - 1;
        if (pre < nt) issue(pre, pre % STAGES);
        cpcommit();

        const uint32_t as = sb  + (ci % STAGES) * ASTG;
        const uint32_t bs = sbB + (ci % STAGES) * BSTG;

        #pragma unroll
        for (int ks = 0; ks < 2; ks++) {
            uint32_t af[4][4];
            uint32_t br0[NJ], br1[NJ];
            #pragma unroll
            for (int i = 0; i < 4; i++)
                ldsm4(af[i][0], af[i][1], af[i][2], af[i][3], as + aoff[i] + ks * 32);
            {
                uint32_t t0, t1, t2, t3;
                ldsm4(t0, t1, t2, t3, bs + boff0 + ks * 32);
                br0[0] = t0; br1[0] = t1; br0[1] = t2; br1[1] = t3;
            }
            if (NJ == 4) {
                uint32_t t0, t1, t2, t3;
                ldsm4(t0, t1, t2, t3, bs + boff1 + ks * 32);
                br0[2] = t0; br1[2] = t1; br0[3] = t2; br1[3] = t3;
            } else {
                uint32_t t0, t1;
                ldsm2(t0, t1, bs + boff1 + ks * 32);
                br0[2] = t0; br1[2] = t1;
            }
            #pragma unroll
            for (int i = 0; i < 4; i++)
                #pragma unroll
                for (int j = 0; j < NJ; j++)
                    mma16816(acc[i][j], af[i][0], af[i][1], af[i][2], af[i][3],
                             br0[j], br1[j]);
        }
    }

    // ---- epilogue ----
    const int g  = lane >> 2;
    const int cq = (lane & 3) * 2;
    #pragma unroll
    for (int mi = 0; mi < 4; mi++) {
        #pragma unroll
        for (int half = 0; half < 2; half++) {
            const int row = bm + wm * 64 + mi * 16 + g + half * 8;
            if (row >= M) continue;
            const int h2 = half * 2;

            if (MODE == 2) {
                // fused LSTM cell: acc[mi][0]=i, [1]=o, [2]=u at h-cols hc..hc+1
                const int t = row / lcnt, loc = lstart + row % lcnt;
                const size_t gn = (size_t)(t * TT + loc) * HH;
                const int hc = blockIdx.x * 32 + wn * 8 + cq;
                float fs0 = 0.f, fs1 = 0.f;
                if (fcsum) {
                    float2 f = *(const float2*)(fcsum + (size_t)row * HH + hc);
                    fs0 = f.x; fs1 = f.y;
                }
                float iv0 = acc[mi][0][h2]     + bias[hc];
                float iv1 = acc[mi][0][h2 + 1] + bias[hc + 1];
                float ov0 = acc[mi][1][h2]     + bias[HH + hc];
                float ov1 = acc[mi][1][h2 + 1] + bias[HH + hc + 1];
                float uv0 = acc[mi][2][h2]     + bias[2 * HH + hc];
                float uv1 = acc[mi][2][h2 + 1] + bias[2 * HH + hc + 1];
                float cn0 = sigmoidf_(iv0) * tanhf(uv0) + fs0;
                float cn1 = sigmoidf_(iv1) * tanhf(uv1) + fs1;
                float hn0 = sigmoidf_(ov0) * tanhf(cn0);
                float hn1 = sigmoidf_(ov1) * tanhf(cn1);
                *(float2*)(cout + gn + hc) = make_float2(cn0, cn1);
                *(float2*)(hout + gn + hc) = make_float2(hn0, hn1);
                *(__half2*)(h16out + gn + hc) = __floats2half2_rn(hn0, hn1);
            } else {
                const float* xrow = nullptr;
                const float* crow = nullptr;
                float* orow;
                if (MODE == 1) {
                    const int t = row / lcnt, loc = lstart + row % lcnt;
                    xrow = xwf  + (size_t)(t * NPAR + (loc - 1) / BRANCH) * HH;
                    crow = cbuf + (size_t)(t * TT + loc) * HH;
                    orow = out  + (size_t)row * HH;
                } else {
                    orow = out + (size_t)row * Nw;
                }
                #pragma unroll
                for (int nj = 0; nj < NJ; nj++) {
                    const int col = bn + wn * 32 + nj * 8 + cq;
                    float v0 = acc[mi][nj][h2];
                    float v1 = acc[mi][nj][h2 + 1];
                    float2 r;
                    if (MODE == 1) {
                        float2 xr = *(const float2*)(xrow + col);
                        float2 cr = *(const float2*)(crow + col);
                        r.x = sigmoidf_(v0 + xr.x) * cr.x;
                        r.y = sigmoidf_(v1 + xr.y) * cr.y;
                    } else {
                        float2 bb = *(const float2*)(bias + col);
                        r.x = v0 + bb.x;
                        r.y = v1 + bb.y;
                    }
                    *(float2*)(orow + col) = r;
                }
            }
        }
    }
}

// ---------------- fp32 -> fp16 cast ----------------
__global__ void cvt16(const float* __restrict__ in, __half* __restrict__ o, int n2) {
    for (int i = blockIdx.x * blockDim.x + threadIdx.x; i < n2;
         i += gridDim.x * blockDim.x) {
        float2 v = ((const float2*)in)[i];
        ((__half2*)o)[i] = __floats2half2_rn(v.x, v.y);
    }
}

// ---------------- weight transpose + fp16 (+optional gate-interleave permute) --------
// PERM: out col n -> n' = (H/8)*24 + g*8 + H%8, g=n/512, H=n%512
template<int PERM>
__global__ void wtrans16(const float* __restrict__ W, __half* __restrict__ Wt,
                         int K, int N)
{
    __shared__ float t[32][33];
    const int bx = blockIdx.x * 32;
    const int by = blockIdx.y * 32;
    const int x = threadIdx.x, y = threadIdx.y;
    #pragma unroll
    for (int i = 0; i < 32; i += 8)
        t[y + i][x] = W[(size_t)(by + y + i) * N + bx + x];
    __syncthreads();
    #pragma unroll
    for (int i = 0; i < 32; i += 8) {
        int n = bx + y + i;
        int np = n;
        if (PERM) {
            int gg = n / HH, Hc = n % HH;
            np = (Hc / 8) * 24 + gg * 8 + (Hc % 8);
        }
        Wt[(size_t)np * K + by + x] = __float2half(t[x][y + i]);
    }
}

// ---------------- child-message reduction ----------------
__global__ void tl_reduce(const float* __restrict__ h, const float* __restrict__ fc,
                          __half* __restrict__ hsum16, float* __restrict__ fcsum,
                          int B, int Pstart, int Pcnt, int Cstart, int Ccnt)
{
    int total = B * Pcnt * HH;
    for (int idx = blockIdx.x * blockDim.x + threadIdx.x; idx < total;
         idx += gridDim.x * blockDim.x) {
        int n = idx & (HH - 1);
        int prow = idx >> 9;
        int t = prow / Pcnt;
        int pl = Pstart + prow % Pcnt;
        float hs = 0.f, fs = 0.f;
        #pragma unroll
        for (int cg = 0; cg < BRANCH; cg++) {
            int cl = BRANCH * pl + 1 + cg;
            if (cl < TT) {
                hs += h[(size_t)(t * TT + cl) * HH + n];
                fs += fc[(size_t)(t * Ccnt + cl - Cstart) * HH + n];
            }
        }
        hsum16[(size_t)prow * HH + n] = __float2half(hs);
        fcsum [(size_t)prow * HH + n] = fs;
    }
}

// ---------------- readout ----------------
__global__ void tl_readout(const float* __restrict__ h, float* __restrict__ out, int B)
{
    int g = blockIdx.x;
    for (int n = threadIdx.x; n < HH; n += blockDim.x) {
        const float* hp = h + (size_t)g * TT * HH + n;
        float s = 0.f;
        #pragma unroll
        for (int tn = 0; tn < TT; tn++) s += hp[(size_t)tn * HH];
        if (n < 256) out[(size_t)g * 256 + n] = s;
        else out[(size_t)B * 256 + (size_t)g * 256 + (n - 256)] = tanhf(s);
    }
}

// ---------------- launch ----------------
extern "C" void kernel_launch(void* const* d_in, const int* in_sizes, int n_in,
                              void* d_out, int out_size)
{
    const float* embed = (const float*)d_in[0];
    const float* W_iou = (const float*)d_in[1];
    const float* U_iou = (const float*)d_in[2];
    const float* b_iou = (const float*)d_in[3];
    const float* W_f   = (const float*)d_in[4];
    const float* U_f   = (const float*)d_in[5];
    const float* b_f   = (const float*)d_in[6];

    int N = in_sizes[0] / D_IN;
    int B = N / TT;
    if (B > MAXB) B = MAXB;

    float *h, *c, *xwf, *fc, *fcsum;
    __half *e16, *h16, *hsum16, *Wt_iou, *Ut_iou, *Wt_f, *Ut_f;
    cudaGetSymbolAddress((void**)&h,      g_h);
    cudaGetSymbolAddress((void**)&c,      g_c);
    cudaGetSymbolAddress((void**)&xwf,    g_xwf);
    cudaGetSymbolAddress((void**)&fc,     g_fc);
    cudaGetSymbolAddress((void**)&fcsum,  g_fcsum);
    cudaGetSymbolAddress((void**)&e16,    g_e16);
    cudaGetSymbolAddress((void**)&h16,    g_h16);
    cudaGetSymbolAddress((void**)&hsum16, g_hsum16);
    cudaGetSymbolAddress((void**)&Wt_iou, g_Wt_iou);
    cudaGetSymbolAddress((void**)&Ut_iou, g_Ut_iou);
    cudaGetSymbolAddress((void**)&Wt_f,   g_Wt_f);
    cudaGetSymbolAddress((void**)&Ut_f,   g_Ut_f);

    const int SM128 = STAGES * (ASTG + 128 * ROWB);   // 61440
    const int SM96  = STAGES * (ASTG + 96 * ROWB);    // 53760
    cudaFuncSetAttribute(hgemm<0,128>, cudaFuncAttributeMaxDynamicSharedMemorySize, SM128);
    cudaFuncSetAttribute(hgemm<1,128>, cudaFuncAttributeMaxDynamicSharedMemorySize, SM128);
    cudaFuncSetAttribute(hgemm<2,96>,  cudaFuncAttributeMaxDynamicSharedMemorySize, SM96);

    cvt16<<<4096, 256>>>(embed, e16, B * TT * D_IN / 2);
    dim3 tb(32, 8);
    wtrans16<1><<<dim3(G3 / 32, D_IN / 32), tb>>>(W_iou, Wt_iou, D_IN, G3);
    wtrans16<1><<<dim3(G3 / 32, HH / 32),   tb>>>(U_iou, Ut_iou, HH,   G3);
    wtrans16<0><<<dim3(HH / 32, D_IN / 32), tb>>>(W_f,   Wt_f,   D_IN, HH);
    wtrans16<0><<<dim3(HH / 32, HH / 32),   tb>>>(U_f,   Ut_f,   HH,   HH);

    #define GY(M) (((M) + 127) / 128)

    // xWf for parent-capable nodes (locals 0..12)
    hgemm<0,128><<<dim3(HH / 128, GY(B * NPAR)), 256, SM128>>>(
        e16, Wt_f, D_IN, D_IN, nullptr, nullptr, 0,
        b_f, nullptr, nullptr, xwf, nullptr, nullptr, nullptr, nullptr,
        B * NPAR, HH, 0, NPAR);

    // level 3 (deepest): fused gates+cell, no children
    hgemm<2,96><<<dim3(G3 / 96, GY(B * 29)), 256, SM96>>>(
        e16, Wt_iou, D_IN, D_IN, nullptr, nullptr, 0,
        b_iou, nullptr, nullptr, nullptr, h, c, h16, nullptr,
        B * 29, G3, 21, 29);

    const int lp[3][4] = { {5, 16, 21, 29}, {1, 4, 5, 16}, {0, 1, 1, 4} };
    for (int li = 0; li < 3; li++) {
        int Pstart = lp[li][0], Pcnt = lp[li][1], Cstart = lp[li][2], Ccnt = lp[li][3];

        // fc = sigmoid(h_child @ U_f + xWf[parent]) * c_child
        hgemm<1,128><<<dim3(HH / 128, GY(B * Ccnt)), 256, SM128>>>(
            h16, Ut_f, HH, HH, nullptr, nullptr, 0,
            nullptr, xwf, c, fc, nullptr, nullptr, nullptr, nullptr,
            B * Ccnt, HH, Cstart, Ccnt);

        tl_reduce<<<2048, 256>>>(h, fc, hsum16, fcsum, B, Pstart, Pcnt, Cstart, Ccnt);

        // fused: gates = E@W_iou + hsum@U_iou + b  ->  cell  -> h, c
        hgemm<2,96><<<dim3(G3 / 96, GY(B * Pcnt)), 256, SM96>>>(
            e16, Wt_iou, D_IN, D_IN, hsum16, Ut_iou, HH,
            b_iou, nullptr, nullptr, nullptr, h, c, h16, fcsum,
            B * Pcnt, G3, Pstart, Pcnt);
    }

    tl_readout<<<B, 256>>>(h, (float*)d_out, B);
    #undef GY
}

// round 5
// speedup vs baseline: 4.0833x; 1.1523x over previous
#include <cuda_runtime.h>
#include <cuda_fp16.h>
#include <cstdint>
#include <math.h>

// ---------------- fixed problem structure ----------------
#define TT      50
#define BRANCH  4
#define D_IN    384
#define HH      512
#define G3      1536
#define MAXB    2000
#define NPAR    13
#define NNODE   (MAXB * TT)

// ---------------- device scratch ----------------
__device__ float  g_c    [(size_t)NNODE * HH];
__device__ float  g_xwf  [(size_t)MAXB * NPAR * HH];
__device__ float  g_fcsum[(size_t)MAXB * 16 * HH];
__device__ __half g_e16  [(size_t)NNODE * D_IN];
__device__ __half g_h16  [(size_t)NNODE * HH];
__device__ __half g_hsum16[(size_t)MAXB * 16 * HH];
__device__ __half g_Wt_iou[G3 * D_IN];   // fp16, K-major [N'][K], gate-interleaved N'
__device__ __half g_Ut_iou[G3 * HH];     // gate-interleaved N'
__device__ __half g_Wt_f  [HH * D_IN];
__device__ __half g_Ut_f  [HH * HH];

// ---------------- PTX helpers (portable ISA: sm_80-level) ----------------
__device__ __forceinline__ uint32_t s2u(const void* p) {
    uint32_t a;
    asm("{ .reg .u64 t; cvta.to.shared.u64 t, %1; cvt.u32.u64 %0, t; }" : "=r"(a) : "l"(p));
    return a;
}
__device__ __forceinline__ void cpasync16(uint32_t dst, const void* src) {
    asm volatile("cp.async.cg.shared.global [%0], [%1], 16;" :: "r"(dst), "l"(src));
}
__device__ __forceinline__ void cpcommit() {
    asm volatile("cp.async.commit_group;" ::: "memory");
}
template<int N>
__device__ __forceinline__ void cpwait() {
    asm volatile("cp.async.wait_group %0;" :: "n"(N) : "memory");
}
__device__ __forceinline__ void ldsm4(uint32_t& r0, uint32_t& r1, uint32_t& r2, uint32_t& r3,
                                      uint32_t a) {
    asm volatile("ldmatrix.sync.aligned.m8n8.x4.shared.b16 {%0,%1,%2,%3}, [%4];"
                 : "=r"(r0), "=r"(r1), "=r"(r2), "=r"(r3) : "r"(a));
}
__device__ __forceinline__ void ldsm2(uint32_t& r0, uint32_t& r1, uint32_t a) {
    asm volatile("ldmatrix.sync.aligned.m8n8.x2.shared.b16 {%0,%1}, [%2];"
                 : "=r"(r0), "=r"(r1) : "r"(a));
}
__device__ __forceinline__ void mma16816(float* c,
                                         uint32_t a0, uint32_t a1, uint32_t a2, uint32_t a3,
                                         uint32_t b0, uint32_t b1) {
    asm volatile(
        "mma.sync.aligned.m16n8k16.row.col.f32.f16.f16.f32 "
        "{%0,%1,%2,%3}, {%4,%5,%6,%7}, {%8,%9}, {%0,%1,%2,%3};"
        : "+f"(c[0]), "+f"(c[1]), "+f"(c[2]), "+f"(c[3])
        : "r"(a0), "r"(a1), "r"(a2), "r"(a3), "r"(b0), "r"(b1));
}
__device__ __forceinline__ float sigmoidf_(float x) { return 1.0f / (1.0f + __expf(-x)); }

// ---------------- GEMM tiling ----------------
#define STAGES 3
#define BK     32                      // halves per k-chunk
#define ROWB   80                      // smem row stride (bytes)
#define ASTG   (128 * ROWB)            // A stage: 128 rows

// MODE 0: out = acc + bias                                        (NT=128)
// MODE 1: fc = sigmoid(acc + xwf[parent]) * c[child];
//         fcsum[parent] = sum over 4 children via shfl            (NT=128)
// MODE 2: fused LSTM cell; gate-interleaved cols (NT=96, warp 64x24 = [i8|o8|u8])
template<int MODE, int NT>
__global__ void __launch_bounds__(256, 2)
hgemm(const __half* __restrict__ A,  const __half* __restrict__ B1, int K1, int strideA,
      const __half* __restrict__ A2, const __half* __restrict__ B2, int K2,
      const float* __restrict__ bias, const float* __restrict__ xwf,
      const float* __restrict__ cbuf,
      float* __restrict__ out,
      float* __restrict__ cout, __half* __restrict__ h16out,
      const float* __restrict__ fcsum, float* __restrict__ fcsum_out,
      int M, int Nw, int lstart, int lcnt, int lvalid, int pcnt)
{
    constexpr int NJ   = NT / 32;
    constexpr int BSTG = NT * ROWB;
    constexpr int NB   = (NT * 4 + 255) / 256;

    extern __shared__ char smraw[];
    const uint32_t sb  = s2u(smraw);
    const uint32_t sbB = sb + STAGES * ASTG;

    const int tid  = threadIdx.x;
    const int lane = tid & 31;
    const int wid  = tid >> 5;
    const int wm   = wid >> 2;
    const int wn   = wid & 3;
    const int bm   = blockIdx.y * 128;
    const int bn   = blockIdx.x * NT;

    // ---- A loader: rows lr0/lr0+64, chunk kc ----
    const int lr0 = tid >> 2;
    const int lr1 = lr0 + 64;
    const int kc  = tid & 3;
    const __half *a1p0, *a1p1, *a2p0 = nullptr, *a2p1 = nullptr;
    {
        int r0 = bm + lr0; if (r0 >= M) r0 = M - 1;
        int r1 = bm + lr1; if (r1 >= M) r1 = M - 1;
        int o0 = r0 % lcnt; if (o0 >= lvalid) o0 = lvalid - 1;
        int o1 = r1 % lcnt; if (o1 >= lvalid) o1 = lvalid - 1;
        int t0 = r0 / lcnt, l0 = lstart + o0;
        int t1 = r1 / lcnt, l1 = lstart + o1;
        a1p0 = A + (size_t)(t0 * TT + l0) * strideA + kc * 8;
        a1p1 = A + (size_t)(t1 * TT + l1) * strideA + kc * 8;
        if (K2 > 0) {
            a2p0 = A2 + (size_t)r0 * K2 + kc * 8;
            a2p1 = A2 + (size_t)r1 * K2 + kc * 8;
        }
    }
    const uint32_t as0 = (uint32_t)(lr0 * ROWB + kc * 16);
    const uint32_t as1 = (uint32_t)(lr1 * ROWB + kc * 16);

    // ---- B loader ----
    const __half* pb1[NB];
    const __half* pb2[NB];
    uint32_t bso[NB];
    bool bok[NB];
    #pragma unroll
    for (int i = 0; i < NB; i++) {
        int idx = tid + i * 256;
        bok[i] = idx < NT * 4;
        int row = bok[i] ? (idx >> 2) : 0;
        int ch  = idx & 3;
        pb1[i] = B1 + (size_t)(bn + row) * K1 + ch * 8;
        pb2[i] = (K2 > 0) ? B2 + (size_t)(bn + row) * K2 + ch * 8 : nullptr;
        bso[i] = (uint32_t)(row * ROWB + ch * 16);
    }

    const int n1 = K1 / BK, n2 = (K2 > 0) ? K2 / BK : 0, nt = n1 + n2;

    auto issue = [&](int ci, int s) {
        const bool p2 = (ci >= n1);
        const int  kb = (p2 ? (ci - n1) : ci) * BK;
        const uint32_t abase = sb  + s * ASTG;
        const uint32_t bbase = sbB + s * BSTG;
        cpasync16(abase + as0, (p2 ? a2p0 : a1p0) + kb);
        cpasync16(abase + as1, (p2 ? a2p1 : a1p1) + kb);
        #pragma unroll
        for (int i = 0; i < NB; i++)
            if (bok[i]) cpasync16(bbase + bso[i], (p2 ? pb2[i] : pb1[i]) + kb);
    };

    // ---- ldmatrix offsets ----
    uint32_t aoff[4];
    {
        const int rl = (lane & 7) + ((lane >> 3) & 1) * 8;
        const int kq = (lane >> 4) * 16;
        #pragma unroll
        for (int i = 0; i < 4; i++)
            aoff[i] = (uint32_t)((wm * 64 + i * 16 + rl) * ROWB + kq);
    }
    const int nl  = (lane & 7) + (lane >> 4) * 8;
    const int kb2 = ((lane >> 3) & 1) * 16;
    const int WNT = NT / 4;
    const uint32_t boff0 = (uint32_t)((wn * WNT + nl) * ROWB + kb2);
    const uint32_t boff1 = (NJ == 4)
        ? (uint32_t)((wn * WNT + 16 + nl) * ROWB + kb2)
        : (uint32_t)((wn * WNT + 16 + (lane & 7)) * ROWB + kb2);

    float acc[4][NJ][4];
    #pragma unroll
    for (int i = 0; i < 4; i++)
        #pragma unroll
        for (int j = 0; j < NJ; j++)
            #pragma unroll
            for (int q = 0; q < 4; q++) acc[i][j][q] = 0.f;

    #pragma unroll
    for (int s = 0; s < STAGES - 1; s++) { issue(s, s); cpcommit(); }

    for (int ci = 0; ci < nt; ci++) {
        cpwait<STAGES - 2>();
        __syncthreads();

        const int pre = ci + STAGES - 1;
        if (pre < nt) issue(pre, pre % STAGES);
        cpcommit();

        const uint32_t as = sb  + (ci % STAGES) * ASTG;
        const uint32_t bs = sbB + (ci % STAGES) * BSTG;

        #pragma unroll
        for (int ks = 0; ks < 2; ks++) {
            uint32_t af[4][4];
            uint32_t br0[NJ], br1[NJ];
            #pragma unroll
            for (int i = 0; i < 4; i++)
                ldsm4(af[i][0], af[i][1], af[i][2], af[i][3], as + aoff[i] + ks * 32);
            {
                uint32_t t0, t1, t2, t3;
                ldsm4(t0, t1, t2, t3, bs + boff0 + ks * 32);
                br0[0] = t0; br1[0] = t1; br0[1] = t2; br1[1] = t3;
            }
            if (NJ == 4) {
                uint32_t t0, t1, t2, t3;
                ldsm4(t0, t1, t2, t3, bs + boff1 + ks * 32);
                br0[2] = t0; br1[2] = t1; br0[3] = t2; br1[3] = t3;
            } else {
                uint32_t t0, t1;
                ldsm2(t0, t1, bs + boff1 + ks * 32);
                br0[2] = t0; br1[2] = t1;
            }
            #pragma unroll
            for (int i = 0; i < 4; i++)
                #pragma unroll
                for (int j = 0; j < NJ; j++)
                    mma16816(acc[i][j], af[i][0], af[i][1], af[i][2], af[i][3],
                             br0[j], br1[j]);
        }
    }

    // ---- epilogue ----
    const int g  = lane >> 2;
    const int cq = (lane & 3) * 2;
    #pragma unroll
    for (int mi = 0; mi < 4; mi++) {
        #pragma unroll
        for (int half = 0; half < 2; half++) {
            const int row = bm + wm * 64 + mi * 16 + half * 8 + g;
            const int h2 = half * 2;

            if (MODE == 1) {
                // fused fc + 4-child fcsum reduction (no branch: shfl needs all lanes)
                const int rc   = (row < M) ? row : M - 1;
                const int t    = rc / lcnt;
                const int off  = rc % lcnt;
                const bool valid = (row < M) && (off < lvalid);
                const int loc  = lstart + ((off < lvalid) ? off : 0);
                const float* xrow = xwf  + (size_t)(t * NPAR + (loc - 1) / BRANCH) * HH;
                const float* crow = cbuf + (size_t)(t * TT + loc) * HH;
                float red[NJ][2];
                #pragma unroll
                for (int nj = 0; nj < NJ; nj++) {
                    const int col = bn + wn * 32 + nj * 8 + cq;
                    float2 xr = *(const float2*)(xrow + col);
                    float2 cr = *(const float2*)(crow + col);
                    float v0 = sigmoidf_(acc[mi][nj][h2]     + xr.x) * cr.x;
                    float v1 = sigmoidf_(acc[mi][nj][h2 + 1] + xr.y) * cr.y;
                    if (!valid) { v0 = 0.f; v1 = 0.f; }
                    v0 += __shfl_xor_sync(0xffffffffu, v0, 4);
                    v0 += __shfl_xor_sync(0xffffffffu, v0, 8);
                    v1 += __shfl_xor_sync(0xffffffffu, v1, 4);
                    v1 += __shfl_xor_sync(0xffffffffu, v1, 8);
                    red[nj][0] = v0; red[nj][1] = v1;
                }
                if ((lane & 12) == 0 && valid) {
                    const size_t pr = (size_t)(t * pcnt + (off >> 2)) * HH;
                    #pragma unroll
                    for (int nj = 0; nj < NJ; nj++) {
                        const int col = bn + wn * 32 + nj * 8 + cq;
                        *(float2*)(fcsum_out + pr + col) = make_float2(red[nj][0], red[nj][1]);
                    }
                }
            } else if (MODE == 2) {
                if (row >= M) continue;
                const int t = row / lcnt, loc = lstart + row % lcnt;
                const size_t gn = (size_t)(t * TT + loc) * HH;
                const int hc = blockIdx.x * 32 + wn * 8 + cq;
                float fs0 = 0.f, fs1 = 0.f;
                if (fcsum) {
                    float2 f = *(const float2*)(fcsum + (size_t)row * HH + hc);
                    fs0 = f.x; fs1 = f.y;
                }
                float iv0 = acc[mi][0][h2]     + bias[hc];
                float iv1 = acc[mi][0][h2 + 1] + bias[hc + 1];
                float ov0 = acc[mi][1][h2]     + bias[HH + hc];
                float ov1 = acc[mi][1][h2 + 1] + bias[HH + hc + 1];
                float uv0 = acc[mi][2][h2]     + bias[2 * HH + hc];
                float uv1 = acc[mi][2][h2 + 1] + bias[2 * HH + hc + 1];
                float cn0 = sigmoidf_(iv0) * tanhf(uv0) + fs0;
                float cn1 = sigmoidf_(iv1) * tanhf(uv1) + fs1;
                float hn0 = sigmoidf_(ov0) * tanhf(cn0);
                float hn1 = sigmoidf_(ov1) * tanhf(cn1);
                *(float2*)(cout + gn + hc) = make_float2(cn0, cn1);
                *(__half2*)(h16out + gn + hc) = __floats2half2_rn(hn0, hn1);
            } else {
                if (row >= M) continue;
                float* orow = out + (size_t)row * Nw;
                #pragma unroll
                for (int nj = 0; nj < NJ; nj++) {
                    const int col = bn + wn * 32 + nj * 8 + cq;
                    float2 bb = *(const float2*)(bias + col);
                    *(float2*)(orow + col) =
                        make_float2(acc[mi][nj][h2] + bb.x, acc[mi][nj][h2 + 1] + bb.y);
                }
            }
        }
    }
}

// ---------------- fp32 -> fp16 cast ----------------
__global__ void cvt16(const float* __restrict__ in, __half* __restrict__ o, int n2) {
    for (int i = blockIdx.x * blockDim.x + threadIdx.x; i < n2;
         i += gridDim.x * blockDim.x) {
        float2 v = ((const float2*)in)[i];
        ((__half2*)o)[i] = __floats2half2_rn(v.x, v.y);
    }
}

// ---------------- weight transpose + fp16 (+optional gate-interleave permute) --------
template<int PERM>
__global__ void wtrans16(const float* __restrict__ W, __half* __restrict__ Wt,
                         int K, int N)
{
    __shared__ float t[32][33];
    const int bx = blockIdx.x * 32;
    const int by = blockIdx.y * 32;
    const int x = threadIdx.x, y = threadIdx.y;
    #pragma unroll
    for (int i = 0; i < 32; i += 8)
        t[y + i][x] = W[(size_t)(by + y + i) * N + bx + x];
    __syncthreads();
    #pragma unroll
    for (int i = 0; i < 32; i += 8) {
        int n = bx + y + i;
        int np = n;
        if (PERM) {
            int gg = n / HH, Hc = n % HH;
            np = (Hc / 8) * 24 + gg * 8 + (Hc % 8);
        }
        Wt[(size_t)np * K + by + x] = __float2half(t[x][y + i]);
    }
}

// ---------------- hsum (fp16 h) + zero-fill fcsum for childless parents ----------
__global__ void tl_hsum(const __half* __restrict__ h16,
                        __half* __restrict__ hsum16, float* __restrict__ fcsum,
                        int B, int Pstart, int Pcnt)
{
    int total = B * Pcnt * HH;
    for (int idx = blockIdx.x * blockDim.x + threadIdx.x; idx < total;
         idx += gridDim.x * blockDim.x) {
        int n = idx & (HH - 1);
        int prow = idx >> 9;
        int t = prow / Pcnt;
        int pl = Pstart + prow % Pcnt;
        float hs = 0.f;
        bool any = false;
        #pragma unroll
        for (int cg = 0; cg < BRANCH; cg++) {
            int cl = BRANCH * pl + 1 + cg;
            if (cl < TT) {
                hs += __half2float(h16[(size_t)(t * TT + cl) * HH + n]);
                any = true;
            }
        }
        hsum16[(size_t)prow * HH + n] = __float2half(hs);
        if (!any) fcsum[(size_t)prow * HH + n] = 0.f;
    }
}

// ---------------- readout ----------------
__global__ void tl_readout(const __half* __restrict__ h16, float* __restrict__ out, int B)
{
    int g = blockIdx.x;
    for (int n = threadIdx.x; n < HH; n += blockDim.x) {
        const __half* hp = h16 + (size_t)g * TT * HH + n;
        float s = 0.f;
        #pragma unroll
        for (int tn = 0; tn < TT; tn++) s += __half2float(hp[(size_t)tn * HH]);
        if (n < 256) out[(size_t)g * 256 + n] = s;
        else out[(size_t)B * 256 + (size_t)g * 256 + (n - 256)] = tanhf(s);
    }
}

// ---------------- launch ----------------
extern "C" void kernel_launch(void* const* d_in, const int* in_sizes, int n_in,
                              void* d_out, int out_size)
{
    const float* embed = (const float*)d_in[0];
    const float* W_iou = (const float*)d_in[1];
    const float* U_iou = (const float*)d_in[2];
    const float* b_iou = (const float*)d_in[3];
    const float* W_f   = (const float*)d_in[4];
    const float* U_f   = (const float*)d_in[5];
    const float* b_f   = (const float*)d_in[6];

    int N = in_sizes[0] / D_IN;
    int B = N / TT;
    if (B > MAXB) B = MAXB;

    float *c, *xwf, *fcsum;
    __half *e16, *h16, *hsum16, *Wt_iou, *Ut_iou, *Wt_f, *Ut_f;
    cudaGetSymbolAddress((void**)&c,      g_c);
    cudaGetSymbolAddress((void**)&xwf,    g_xwf);
    cudaGetSymbolAddress((void**)&fcsum,  g_fcsum);
    cudaGetSymbolAddress((void**)&e16,    g_e16);
    cudaGetSymbolAddress((void**)&h16,    g_h16);
    cudaGetSymbolAddress((void**)&hsum16, g_hsum16);
    cudaGetSymbolAddress((void**)&Wt_iou, g_Wt_iou);
    cudaGetSymbolAddress((void**)&Ut_iou, g_Ut_iou);
    cudaGetSymbolAddress((void**)&Wt_f,   g_Wt_f);
    cudaGetSymbolAddress((void**)&Ut_f,   g_Ut_f);

    const int SM128 = STAGES * (ASTG + 128 * ROWB);   // 61440
    const int SM96  = STAGES * (ASTG + 96 * ROWB);    // 53760
    cudaFuncSetAttribute(hgemm<0,128>, cudaFuncAttributeMaxDynamicSharedMemorySize, SM128);
    cudaFuncSetAttribute(hgemm<1,128>, cudaFuncAttributeMaxDynamicSharedMemorySize, SM128);
    cudaFuncSetAttribute(hgemm<2,96>,  cudaFuncAttributeMaxDynamicSharedMemorySize, SM96);

    cvt16<<<4096, 256>>>(embed, e16, B * TT * D_IN / 2);
    dim3 tb(32, 8);
    wtrans16<1><<<dim3(G3 / 32, D_IN / 32), tb>>>(W_iou, Wt_iou, D_IN, G3);
    wtrans16<1><<<dim3(G3 / 32, HH / 32),   tb>>>(U_iou, Ut_iou, HH,   G3);
    wtrans16<0><<<dim3(HH / 32, D_IN / 32), tb>>>(W_f,   Wt_f,   D_IN, HH);
    wtrans16<0><<<dim3(HH / 32, HH / 32),   tb>>>(U_f,   Ut_f,   HH,   HH);

    #define GY(M) (((M) + 127) / 128)

    // xWf for parent-capable nodes (locals 0..12)
    hgemm<0,128><<<dim3(HH / 128, GY(B * NPAR)), 256, SM128>>>(
        e16, Wt_f, D_IN, D_IN, nullptr, nullptr, 0,
        b_f, nullptr, nullptr, xwf, nullptr, nullptr, nullptr, nullptr,
        B * NPAR, HH, 0, NPAR, NPAR, 0);

    // level 3 (deepest): fused gates+cell, no children
    hgemm<2,96><<<dim3(G3 / 96, GY(B * 29)), 256, SM96>>>(
        e16, Wt_iou, D_IN, D_IN, nullptr, nullptr, 0,
        b_iou, nullptr, nullptr, nullptr, c, h16, nullptr, nullptr,
        B * 29, G3, 21, 29, 29, 0);

    // {Pstart, Pcnt, Cstart, CcntPad, CcntValid}
    const int lp[3][5] = { {5, 16, 21, 32, 29}, {1, 4, 5, 16, 16}, {0, 1, 1, 4, 4} };
    for (int li = 0; li < 3; li++) {
        int Pstart = lp[li][0], Pcnt = lp[li][1], Cstart = lp[li][2];
        int Cpad = lp[li][3], Cval = lp[li][4];

        // fc = sigmoid(h_child @ U_f + xWf[parent]) * c_child; fcsum fused via shfl
        hgemm<1,128><<<dim3(HH / 128, GY(B * Cpad)), 256, SM128>>>(
            h16, Ut_f, HH, HH, nullptr, nullptr, 0,
            nullptr, xwf, c, nullptr, nullptr, nullptr, nullptr, fcsum,
            B * Cpad, HH, Cstart, Cpad, Cval, Pcnt);

        tl_hsum<<<1024, 256>>>(h16, hsum16, fcsum, B, Pstart, Pcnt);

        // fused: gates = E@W_iou + hsum@U_iou + b  ->  cell  -> h16, c
        hgemm<2,96><<<dim3(G3 / 96, GY(B * Pcnt)), 256, SM96>>>(
            e16, Wt_iou, D_IN, D_IN, hsum16, Ut_iou, HH,
            b_iou, nullptr, nullptr, nullptr, c, h16, fcsum, nullptr,
            B * Pcnt, G3, Pstart, Pcnt, Pcnt, 0);
    }

    tl_readout<<<B, 256>>>(h16, (float*)d_out, B);
    #undef GY
}